// round 1
// baseline (speedup 1.0000x reference)
#include <cuda_runtime.h>

// BiGRU: B=64, S=4096, D_in=7, H=128, 2 layers, bidirectional, fp32.
// Plan:
//   k_gx0 : gx0[t] = x[t] @ Wih0^T + bih0  for both dirs  -> g_gx [tok][768]
//   k_rec : per-(batch,dir) persistent recurrence (128 CTAs), weights in regs,
//           f32x2 packed FMA, h broadcast via smem. writes g_hio [tok][256]
//   k_gemm: gx1 = h1in @ Wih1^T + bih1 (SIMT f32x2 tiled GEMM) -> g_gx (reused)
//   k_rec : layer 1
//   k_head: logits = h1out @ wout^T + bout

#define BB   64
#define SS   4096
#define DIN  7
#define HH   128
#define G3   384
#define NTOK (BB * SS)          // 262144

// ---------------- scratch (device globals; reused across phases) -------------
__device__ float g_gx [ (size_t)NTOK * 768 ];   // gate pre-activations [f384|b384]
__device__ float g_hio[ (size_t)NTOK * 256 ];   // layer in/out hidden  [f128|b128]

// ---------------- f32x2 helpers ----------------------------------------------
__device__ __forceinline__ unsigned long long ffma2(unsigned long long a,
                                                    unsigned long long b,
                                                    unsigned long long c) {
    unsigned long long d;
    asm("fma.rn.f32x2 %0, %1, %2, %3;" : "=l"(d) : "l"(a), "l"(b), "l"(c));
    return d;
}
__device__ __forceinline__ unsigned long long dup2(float x) {
    unsigned long long d;
    asm("mov.b64 %0, {%1, %1};" : "=l"(d) : "f"(x));
    return d;
}
__device__ __forceinline__ float2 unpk(unsigned long long v) {
    float2 r;
    asm("mov.b64 {%0, %1}, %2;" : "=f"(r.x), "=f"(r.y) : "l"(v));
    return r;
}

__device__ __forceinline__ float sigf(float x) {
    return __fdividef(1.f, 1.f + __expf(-x));
}
__device__ __forceinline__ float tanhfast(float x) {
    // tanh(x) = 1 - 2/(e^{2x}+1); saturates cleanly for |x| large
    return 1.f - __fdividef(2.f, __expf(2.f * x) + 1.f);
}

// ---------------- layer-0 input projection (K=7) ------------------------------
__global__ void k_gx0(const float* __restrict__ x,
                      const float* __restrict__ wf, const float* __restrict__ bf,
                      const float* __restrict__ wb, const float* __restrict__ bb) {
    __shared__ float sx[8 * DIN];
    int j = threadIdx.x;                       // 0..767
    long long token0 = (long long)blockIdx.x * 8;
    int dir = (j >= G3);
    int jj = dir ? j - G3 : j;
    const float* wrow = (dir ? wb : wf) + jj * DIN;
    float w0 = wrow[0], w1 = wrow[1], w2 = wrow[2], w3 = wrow[3];
    float w4 = wrow[4], w5 = wrow[5], w6 = wrow[6];
    float bias = (dir ? bb : bf)[jj];
    if (j < 8 * DIN) sx[j] = x[token0 * DIN + j];
    __syncthreads();
#pragma unroll
    for (int tk = 0; tk < 8; tk++) {
        const float* xs = sx + tk * DIN;
        float v = bias;
        v = fmaf(w0, xs[0], v); v = fmaf(w1, xs[1], v); v = fmaf(w2, xs[2], v);
        v = fmaf(w3, xs[3], v); v = fmaf(w4, xs[4], v); v = fmaf(w5, xs[5], v);
        v = fmaf(w6, xs[6], v);
        g_gx[(token0 + tk) * 768 + j] = v;
    }
}

// ---------------- recurrence: one CTA per (batch, dir) ------------------------
// 384 threads; thread j owns gate-row j (Whh row in 64 packed f32x2 regs).
// Per step: gh_j = <Whh_j, h> + bhh_j  (f32x2, h broadcast from smem),
// pointwise r/z/n gates on threads j<128, h -> smem + gmem.
__global__ void __launch_bounds__(384, 1) k_rec(
    const float* __restrict__ whh_f, const float* __restrict__ bhh_f,
    const float* __restrict__ whh_b, const float* __restrict__ bhh_b) {
    __shared__ __align__(16) float s_h[HH];
    __shared__ float s_a[G3];
    __shared__ float s_b[G3];

    int j   = threadIdx.x;
    int b   = blockIdx.x >> 1;
    int dir = blockIdx.x & 1;

    const float* whh = dir ? whh_b : whh_f;
    float bhh = (dir ? bhh_b : bhh_f)[j];

    unsigned long long w[64];
    const unsigned long long* wp =
        (const unsigned long long*)(whh + (size_t)j * HH);
#pragma unroll
    for (int i = 0; i < 64; i++) w[i] = wp[i];

    if (j < HH) s_h[j] = 0.f;
    float hreg = 0.f;

    long long tokbase = (long long)b * SS;
    int t0 = dir ? (SS - 1) : 0;
    long long gstr = dir ? -768 : 768;
    long long hstr = dir ? -256 : 256;

    const float* gp = g_gx + (tokbase + t0) * 768 + (long long)dir * G3 + j;
    float*       hp = g_hio + (tokbase + t0) * 256 + (long long)dir * HH + j;

    float gx_next = *gp;
    __syncthreads();

    for (int tt = 0; tt < SS; tt++) {
        float gxv = gx_next;
        gp += gstr;
        if (tt + 1 < SS) gx_next = *gp;          // prefetch next step

        // gh = dot(Whh_j, h) + bhh_j  (packed f32x2)
        unsigned long long a0 = 0ull, a1 = 0ull;
        const ulonglong2* hv = (const ulonglong2*)s_h;
#pragma unroll
        for (int k = 0; k < 32; k++) {
            ulonglong2 hk = hv[k];               // LDS.128, warp-uniform (broadcast)
            a0 = ffma2(w[2 * k],     hk.x, a0);
            a1 = ffma2(w[2 * k + 1], hk.y, a1);
        }
        float2 f0 = unpk(a0), f1 = unpk(a1);
        float gh = (f0.x + f0.y) + (f1.x + f1.y) + bhh;

        s_a[j] = gxv;
        s_b[j] = gh;
        __syncthreads();

        if (j < HH) {
            float r = sigf(s_a[j]        + s_b[j]);
            float z = sigf(s_a[HH + j]   + s_b[HH + j]);
            float n = tanhfast(fmaf(r, s_b[2 * HH + j], s_a[2 * HH + j]));
            hreg = fmaf(z, hreg - n, n);         // (1-z)*n + z*h
            s_h[j] = hreg;
            *hp = hreg;
            hp += hstr;
        }
        __syncthreads();
    }
}

// ---------------- layer-1 input GEMM: gx1 = h1in @ Wih1^T + bih1 --------------
// C[262144 x 768] = A[262144 x 256] * W[768 x 256]^T ; tiles 128x128x16,
// 256 threads, 8x8 per thread with packed f32x2 accumulators.
__global__ void __launch_bounds__(256) k_gemm(
    const float* __restrict__ Wf, const float* __restrict__ bf,
    const float* __restrict__ Wb, const float* __restrict__ bb) {
    __shared__ __align__(16) float As[16][132];
    __shared__ __align__(16) float Bs[16][132];

    int tid = threadIdx.x;
    int mt = blockIdx.x, nt = blockIdx.y;
    const float* W    = (nt < 3) ? Wf : Wb;
    const float* bias = (nt < 3) ? bf : bb;
    int n0loc = (nt % 3) * 128;                  // row offset inside W (per dir)
    long long m0 = (long long)mt * 128;
    const float* Ab = g_hio + m0 * 256;

    int ty = tid >> 4;                           // m-group 0..15
    int tx = tid & 15;                           // n-group 0..15

    unsigned long long acc[8][4];
#pragma unroll
    for (int i = 0; i < 8; i++)
#pragma unroll
        for (int p = 0; p < 4; p++) acc[i][p] = 0ull;

    for (int kt = 0; kt < 256; kt += 16) {
#pragma unroll
        for (int i = 0; i < 2; i++) {
            int task = tid + i * 256;            // 512 float4 loads each for A and W
            int m = task >> 2, kc = task & 3;
            float4 v = *(const float4*)(Ab + (size_t)m * 256 + kt + kc * 4);
            As[kc * 4 + 0][m] = v.x; As[kc * 4 + 1][m] = v.y;
            As[kc * 4 + 2][m] = v.z; As[kc * 4 + 3][m] = v.w;
            float4 u = *(const float4*)(W + (size_t)(n0loc + m) * 256 + kt + kc * 4);
            Bs[kc * 4 + 0][m] = u.x; Bs[kc * 4 + 1][m] = u.y;
            Bs[kc * 4 + 2][m] = u.z; Bs[kc * 4 + 3][m] = u.w;
        }
        __syncthreads();
#pragma unroll
        for (int k = 0; k < 16; k++) {
            float4 va0 = *(const float4*)&As[k][ty * 8];
            float4 va1 = *(const float4*)&As[k][ty * 8 + 4];
            ulonglong2 vb0 = *(const ulonglong2*)&Bs[k][tx * 8];
            ulonglong2 vb1 = *(const ulonglong2*)&Bs[k][tx * 8 + 4];
            unsigned long long bp0 = vb0.x, bp1 = vb0.y, bp2 = vb1.x, bp3 = vb1.y;
            float am[8] = {va0.x, va0.y, va0.z, va0.w, va1.x, va1.y, va1.z, va1.w};
#pragma unroll
            for (int m = 0; m < 8; m++) {
                unsigned long long ad = dup2(am[m]);
                acc[m][0] = ffma2(ad, bp0, acc[m][0]);
                acc[m][1] = ffma2(ad, bp1, acc[m][1]);
                acc[m][2] = ffma2(ad, bp2, acc[m][2]);
                acc[m][3] = ffma2(ad, bp3, acc[m][3]);
            }
        }
        __syncthreads();
    }

    int ngl = nt * 128 + tx * 8;                 // global col in [0,768)
    float bias8[8];
#pragma unroll
    for (int q = 0; q < 8; q++) bias8[q] = bias[n0loc + tx * 8 + q];
#pragma unroll
    for (int m = 0; m < 8; m++) {
        long long gm = m0 + ty * 8 + m;
        float* crow = g_gx + gm * 768 + ngl;
        float o[8];
#pragma unroll
        for (int p = 0; p < 4; p++) {
            float2 f = unpk(acc[m][p]);
            o[2 * p]     = f.x + bias8[2 * p];
            o[2 * p + 1] = f.y + bias8[2 * p + 1];
        }
        *(float4*)(crow)     = make_float4(o[0], o[1], o[2], o[3]);
        *(float4*)(crow + 4) = make_float4(o[4], o[5], o[6], o[7]);
    }
}

// ---------------- output head: logits = h1out @ wout^T + bout -----------------
__global__ void k_head(const float* __restrict__ wout,
                       const float* __restrict__ bout,
                       float* __restrict__ out) {
    int warp = threadIdx.x >> 5, lane = threadIdx.x & 31;
    long long token = (long long)blockIdx.x * 8 + warp;
    const float* hrow = g_hio + token * 256;
    float acc = 0.f;
#pragma unroll
    for (int i = 0; i < 8; i++) {
        int c = lane + i * 32;
        acc = fmaf(hrow[c], wout[c], acc);
    }
#pragma unroll
    for (int off = 16; off; off >>= 1)
        acc += __shfl_xor_sync(0xffffffffu, acc, off);
    if (lane == 0) out[token] = acc + bout[0];
}

// ---------------- launch ------------------------------------------------------
extern "C" void kernel_launch(void* const* d_in, const int* in_sizes, int n_in,
                              void* d_out, int out_size) {
    const float* x     = (const float*)d_in[0];
    const float* wih0f = (const float*)d_in[1];
    const float* whh0f = (const float*)d_in[2];
    const float* bih0f = (const float*)d_in[3];
    const float* bhh0f = (const float*)d_in[4];
    const float* wih0b = (const float*)d_in[5];
    const float* whh0b = (const float*)d_in[6];
    const float* bih0b = (const float*)d_in[7];
    const float* bhh0b = (const float*)d_in[8];
    const float* wih1f = (const float*)d_in[9];
    const float* whh1f = (const float*)d_in[10];
    const float* bih1f = (const float*)d_in[11];
    const float* bhh1f = (const float*)d_in[12];
    const float* wih1b = (const float*)d_in[13];
    const float* whh1b = (const float*)d_in[14];
    const float* bih1b = (const float*)d_in[15];
    const float* bhh1b = (const float*)d_in[16];
    const float* wout  = (const float*)d_in[17];
    const float* bout  = (const float*)d_in[18];
    float* out = (float*)d_out;

    k_gx0 <<<NTOK / 8, 768>>>(x, wih0f, bih0f, wih0b, bih0b);
    k_rec <<<128, 384>>>(whh0f, bhh0f, whh0b, bhh0b);
    k_gemm<<<dim3(2048, 6), 256>>>(wih1f, bih1f, wih1b, bih1b);
    k_rec <<<128, 384>>>(whh1f, bhh1f, whh1b, bhh1b);
    k_head<<<NTOK / 8, 256>>>(wout, bout, out);
}